// round 1
// baseline (speedup 1.0000x reference)
#include <cuda_runtime.h>
#include <math.h>

// Qwen3.5 TopK Router — fused GEMM + softmax + top-8 + renorm (fp32 baseline)
// T=16384 tokens, D=2048, E=128 experts, K=8.
// Output layout (float32, concatenated, reference return order):
//   [0,              T*E)            router_logits (softmax probs)
//   [T*E,            T*E + T*K)      router_weights (renormalized top-8)
//   [T*E + T*K,      T*E + 2*T*K)    router_indices (as float)

#define D_DIM    2048
#define E_EXP    128
#define TOPK     8
#define BT       64       // tokens per block
#define DC       16       // k-chunk depth
#define NTHREADS 128
#define LPAD     129      // padded logits row (bank-conflict avoidance)

__global__ __launch_bounds__(NTHREADS, 3)
void router_kernel(const float* __restrict__ X,
                   const float* __restrict__ W,
                   float* __restrict__ out, int T)
{
    // Aliased shared buffer:
    //   mainloop: Xs[2][DC][BT] (2048 f) + Ws[2][DC][E] (4096 f) = 6144 floats
    //   epilogue: Ls[BT][LPAD] = 8256 floats
    __shared__ __align__(16) float sb[BT * LPAD];
    __shared__ float smax[BT];
    __shared__ float srsum[BT];

    float* Xs = sb;                    // [2][DC][BT]
    float* Ws = sb + 2 * DC * BT;      // [2][DC][E_EXP]

    const int tid  = threadIdx.x;
    const int tx   = tid & 15;         // expert group (16 groups x 8 experts)
    const int ty   = tid >> 4;         // token group  (8 groups x 8 tokens)
    const int row0 = blockIdx.x * BT;

    const float* Xblk = X + (size_t)row0 * D_DIM;

    // X loader mapping: 2 threads per token row, 8 k-values each
    const int xt = tid >> 1;           // token 0..63
    const int xh = (tid & 1) * 8;      // k sub-offset {0,8}
    // W loader mapping: thread tid owns expert row tid (16 k-values)

    float acc[8][8];
    #pragma unroll
    for (int i = 0; i < 8; i++)
        #pragma unroll
        for (int j = 0; j < 8; j++) acc[i][j] = 0.0f;

    float4 xr0, xr1, wr0, wr1, wr2, wr3;

    // ---- prologue: load chunk 0 into buffer 0 ----
    {
        const float* xp = Xblk + (size_t)xt * D_DIM + xh;
        xr0 = *(const float4*)(xp);
        xr1 = *(const float4*)(xp + 4);
        const float* wp = W + (size_t)tid * D_DIM;
        wr0 = *(const float4*)(wp);
        wr1 = *(const float4*)(wp + 4);
        wr2 = *(const float4*)(wp + 8);
        wr3 = *(const float4*)(wp + 12);

        float xv[8] = {xr0.x, xr0.y, xr0.z, xr0.w, xr1.x, xr1.y, xr1.z, xr1.w};
        #pragma unroll
        for (int m = 0; m < 8; m++) Xs[(xh + m) * BT + xt] = xv[m];
        float wv[16] = {wr0.x, wr0.y, wr0.z, wr0.w, wr1.x, wr1.y, wr1.z, wr1.w,
                        wr2.x, wr2.y, wr2.z, wr2.w, wr3.x, wr3.y, wr3.z, wr3.w};
        #pragma unroll
        for (int m = 0; m < 16; m++) Ws[m * E_EXP + tid] = wv[m];
    }
    __syncthreads();

    const int NC = D_DIM / DC;  // 128 chunks
    for (int c = 0; c < NC; ++c) {
        const int cur = c & 1;
        const int nxt = cur ^ 1;

        // prefetch next chunk into registers (global latency overlapped)
        if (c + 1 < NC) {
            const int kc = (c + 1) * DC;
            const float* xp = Xblk + (size_t)xt * D_DIM + kc + xh;
            xr0 = *(const float4*)(xp);
            xr1 = *(const float4*)(xp + 4);
            const float* wp = W + (size_t)tid * D_DIM + kc;
            wr0 = *(const float4*)(wp);
            wr1 = *(const float4*)(wp + 4);
            wr2 = *(const float4*)(wp + 8);
            wr3 = *(const float4*)(wp + 12);
        }

        // compute on current buffer
        const float* Xc = Xs + cur * (DC * BT);
        const float* Wc = Ws + cur * (DC * E_EXP);
        #pragma unroll
        for (int k = 0; k < DC; k++) {
            float4 a0 = *(const float4*)(Xc + k * BT + ty * 8);
            float4 a1 = *(const float4*)(Xc + k * BT + ty * 8 + 4);
            float4 b0 = *(const float4*)(Wc + k * E_EXP + tx * 8);
            float4 b1 = *(const float4*)(Wc + k * E_EXP + tx * 8 + 4);
            float xf[8] = {a0.x, a0.y, a0.z, a0.w, a1.x, a1.y, a1.z, a1.w};
            float wf[8] = {b0.x, b0.y, b0.z, b0.w, b1.x, b1.y, b1.z, b1.w};
            #pragma unroll
            for (int i = 0; i < 8; i++)
                #pragma unroll
                for (int j = 0; j < 8; j++)
                    acc[i][j] = fmaf(xf[i], wf[j], acc[i][j]);
        }

        // commit prefetched chunk into the other buffer
        if (c + 1 < NC) {
            float* Xn = Xs + nxt * (DC * BT);
            float* Wn = Ws + nxt * (DC * E_EXP);
            float xv[8] = {xr0.x, xr0.y, xr0.z, xr0.w, xr1.x, xr1.y, xr1.z, xr1.w};
            #pragma unroll
            for (int m = 0; m < 8; m++) Xn[(xh + m) * BT + xt] = xv[m];
            float wv[16] = {wr0.x, wr0.y, wr0.z, wr0.w, wr1.x, wr1.y, wr1.z, wr1.w,
                            wr2.x, wr2.y, wr2.z, wr2.w, wr3.x, wr3.y, wr3.z, wr3.w};
            #pragma unroll
            for (int m = 0; m < 16; m++) Wn[m * E_EXP + tid] = wv[m];
        }
        __syncthreads();
    }

    // ---- epilogue: logits -> smem (aliases mainloop buffers; all reads done) ----
    float* Ls = sb;  // [BT][LPAD]
    #pragma unroll
    for (int i = 0; i < 8; i++)
        #pragma unroll
        for (int j = 0; j < 8; j++)
            Ls[(ty * 8 + i) * LPAD + (tx * 8 + j)] = acc[i][j];
    __syncthreads();

    // per-token max & exp-sum
    if (tid < BT) {
        const float* r = Ls + tid * LPAD;
        float m = r[0];
        #pragma unroll 4
        for (int e = 1; e < E_EXP; e++) m = fmaxf(m, r[e]);
        float s = 0.0f;
        #pragma unroll 4
        for (int e = 0; e < E_EXP; e++) s += __expf(r[e] - m);
        smax[tid]  = m;
        srsum[tid] = 1.0f / s;
    }
    __syncthreads();

    // softmax probs: overwrite smem + coalesced global write of router_logits
    for (int i = tid; i < BT * E_EXP; i += NTHREADS) {
        int t = i >> 7;
        int e = i & 127;
        float p = __expf(Ls[t * LPAD + e] - smax[t]) * srsum[t];
        Ls[t * LPAD + e] = p;
        out[(size_t)(row0 + t) * E_EXP + e] = p;
    }
    __syncthreads();

    // top-8 (strict > keeps lowest index on ties, matching jax top_k) + renorm
    if (tid < BT) {
        float* r = Ls + tid * LPAD;
        float vals[TOPK];
        int   idxs[TOPK];
        float s = 0.0f;
        #pragma unroll
        for (int k = 0; k < TOPK; k++) {
            float bv = -1.0f;
            int   bi = 0;
            for (int e = 0; e < E_EXP; e++) {
                float v = r[e];
                if (v > bv) { bv = v; bi = e; }
            }
            r[bi]   = -1.0f;  // probs are > 0, safe sentinel
            vals[k] = bv;
            idxs[k] = bi;
            s += bv;
        }
        float rs = 1.0f / s;
        size_t base_w = (size_t)T * E_EXP + (size_t)(row0 + tid) * TOPK;
        size_t base_i = (size_t)T * E_EXP + (size_t)T * TOPK + (size_t)(row0 + tid) * TOPK;
        #pragma unroll
        for (int k = 0; k < TOPK; k++) {
            out[base_w + k] = vals[k] * rs;
            out[base_i + k] = (float)idxs[k];
        }
    }
}

extern "C" void kernel_launch(void* const* d_in, const int* in_sizes, int n_in,
                              void* d_out, int out_size)
{
    const float* X = (const float*)d_in[0];   // hidden_states [T, 2048]
    const float* W = (const float*)d_in[1];   // weight        [128, 2048]
    float* out = (float*)d_out;

    const int T = in_sizes[0] / D_DIM;        // 16384
    dim3 grid(T / BT);                        // 256 blocks
    router_kernel<<<grid, NTHREADS>>>(X, W, out, T);
}

// round 3
// speedup vs baseline: 1.7527x; 1.7527x over previous
#include <cuda_runtime.h>
#include <cstdint>
#include <math.h>

// Qwen3.5 TopK Router — 3xTF32 mma.sync GEMM + fused softmax/top-8/renorm.
// (tcgen05 unavailable: harness ptxas target is plain sm_103, no 'a' features.)
// T=16384, D=2048, E=128, K=8.
// Grid: 128 CTAs x 256 threads (8 warps). CTA tile: 128 tokens x 128 experts.
// K loop: 64 chunks of 32. fp32 split x = hi + lo (tf32 each);
// acc += Ahi*Bhi + Ahi*Blo + Alo*Bhi  (fp32 accum) -> fp32-grade logits.
//
// Output layout (float32): [T*E logits][T*K weights][T*K indices-as-float]

#define D_DIM  2048
#define E_EXP  128
#define TOPK   8
#define BM     128
#define KC     32
#define NC     (D_DIM / KC)     // 64
#define NT     256
#define LPAD   129

// stage layout in dynamic smem (floats): Ahi | Alo | Bhi | Blo, 4096 each
#define TILE_F  4096            // 128 rows x 32 cols
#define STAGE_F (4 * TILE_F)    // 16384 floats = 64 KB
#define SMEM_F  (2 * STAGE_F)   // 131072 B total

static __device__ __forceinline__ float ftf32(float x) {
    uint32_t u;
    asm("cvt.rna.tf32.f32 %0, %1;" : "=r"(u) : "f"(x));
    return __uint_as_float(u);
}

#define MMA_TF32(d, a, b)                                                     \
    asm volatile(                                                             \
        "mma.sync.aligned.m16n8k8.row.col.f32.tf32.tf32.f32 "                 \
        "{%0,%1,%2,%3}, {%4,%5,%6,%7}, {%8,%9}, {%0,%1,%2,%3};"               \
        : "+f"((d)[0]), "+f"((d)[1]), "+f"((d)[2]), "+f"((d)[3])              \
        : "r"(__float_as_uint((a)[0])), "r"(__float_as_uint((a)[1])),         \
          "r"(__float_as_uint((a)[2])), "r"(__float_as_uint((a)[3])),         \
          "r"(__float_as_uint((b)[0])), "r"(__float_as_uint((b)[1])))

__global__ __launch_bounds__(NT, 1)
void router_mma(const float* __restrict__ X,
                const float* __restrict__ W,
                float* __restrict__ out, int T)
{
    extern __shared__ __align__(16) float smem[];
    __shared__ float smax[BM];
    __shared__ float srsum[BM];

    const int tid  = threadIdx.x;
    const int wid  = tid >> 5;
    const int lane = tid & 31;
    const int row0 = blockIdx.x * BM;

    // ---------------- producer mapping ----------------
    // warp w loads rows 16w..16w+15 of both A (tokens) and B (experts).
    // LDG q (0..3): row = 16w + 4q + (lane>>3), cols (lane&7)*4 .. +3  (coalesced)
    const int prow_sub = lane >> 3;          // 0..3
    const int pcol     = (lane & 7) * 4;     // 0..28
    const float* gA = X + (size_t)(row0 + 16 * wid + prow_sub) * D_DIM + pcol;
    const float* gB = W + (size_t)(16 * wid + prow_sub) * D_DIM + pcol;

    // swizzled smem float index for (row r, col f): r*32 + (f ^ ((r&7)<<2))
    int sidx[4];
    #pragma unroll
    for (int q = 0; q < 4; q++) {
        const int r = 16 * wid + 4 * q + prow_sub;
        sidx[q] = r * 32 + (pcol ^ ((r & 7) << 2));
    }

    // ---------------- consumer mapping ----------------
    // warp grid 4(M) x 2(N): warp tile 32 tokens x 64 experts
    const int g  = lane >> 2;                // 0..7
    const int tg = lane & 3;                 // 0..3
    const int mrow0 = (wid & 3) * 32;
    const int ncol0 = (wid >> 2) * 64;
    const int cbase = tg ^ (g << 2);         // swizzled col base (k index enc.)
    const int arow0 = (mrow0 + g) * 32;      // float offset of A row (g)
    const int brow0 = (ncol0 + g) * 32;      // float offset of B row (expert g)

    float acc[2][8][4];
    #pragma unroll
    for (int mt = 0; mt < 2; mt++)
        #pragma unroll
        for (int nt = 0; nt < 8; nt++)
            #pragma unroll
            for (int i = 0; i < 4; i++) acc[mt][nt][i] = 0.0f;

    float4 ra[4], rb[4];

    // ---- prologue: chunk 0 -> stage 0 ----
    #pragma unroll
    for (int q = 0; q < 4; q++) {
        ra[q] = *(const float4*)(gA + (size_t)q * 4 * D_DIM);
        rb[q] = *(const float4*)(gB + (size_t)q * 4 * D_DIM);
    }
    {
        float* Ah = smem;            float* Al = smem + TILE_F;
        float* Bh = smem + 2*TILE_F; float* Bl = smem + 3*TILE_F;
        #pragma unroll
        for (int q = 0; q < 4; q++) {
            float4 v = ra[q];
            float hx=ftf32(v.x), hy=ftf32(v.y), hz=ftf32(v.z), hw=ftf32(v.w);
            *(float4*)(Ah + sidx[q]) = make_float4(hx, hy, hz, hw);
            *(float4*)(Al + sidx[q]) = make_float4(ftf32(v.x-hx), ftf32(v.y-hy),
                                                   ftf32(v.z-hz), ftf32(v.w-hw));
            float4 u = rb[q];
            float jx=ftf32(u.x), jy=ftf32(u.y), jz=ftf32(u.z), jw=ftf32(u.w);
            *(float4*)(Bh + sidx[q]) = make_float4(jx, jy, jz, jw);
            *(float4*)(Bl + sidx[q]) = make_float4(ftf32(u.x-jx), ftf32(u.y-jy),
                                                   ftf32(u.z-jz), ftf32(u.w-jw));
        }
    }
    __syncthreads();

    // ---- main loop ----
    for (int c = 0; c < NC; ++c) {
        // prefetch next chunk (global latency overlaps compute)
        if (c + 1 < NC) {
            const int ko = (c + 1) * KC;
            #pragma unroll
            for (int q = 0; q < 4; q++) {
                ra[q] = *(const float4*)(gA + (size_t)q * 4 * D_DIM + ko);
                rb[q] = *(const float4*)(gB + (size_t)q * 4 * D_DIM + ko);
            }
        }

        // compute on current stage
        {
            const float* Ah = smem + (c & 1) * STAGE_F;
            const float* Al = Ah + TILE_F;
            const float* Bh = Ah + 2 * TILE_F;
            const float* Bl = Ah + 3 * TILE_F;

            #pragma unroll
            for (int kb = 0; kb < 4; kb++) {
                const int c0 = cbase ^ (kb * 8);
                const int c1 = c0 ^ 4;

                float ah[2][4], al[2][4];
                #pragma unroll
                for (int mt = 0; mt < 2; mt++) {
                    const int ro = arow0 + mt * 512;     // 16 rows = 512 floats
                    ah[mt][0] = Ah[ro + c0];
                    ah[mt][1] = Ah[ro + 256 + c0];       // +8 rows
                    ah[mt][2] = Ah[ro + c1];
                    ah[mt][3] = Ah[ro + 256 + c1];
                    al[mt][0] = Al[ro + c0];
                    al[mt][1] = Al[ro + 256 + c0];
                    al[mt][2] = Al[ro + c1];
                    al[mt][3] = Al[ro + 256 + c1];
                }
                float bh[8][2], bl[8][2];
                #pragma unroll
                for (int nt = 0; nt < 8; nt++) {
                    const int ro = brow0 + nt * 256;     // 8 experts = 256 floats
                    bh[nt][0] = Bh[ro + c0];
                    bh[nt][1] = Bh[ro + c1];
                    bl[nt][0] = Bl[ro + c0];
                    bl[nt][1] = Bl[ro + c1];
                }

                #pragma unroll
                for (int mt = 0; mt < 2; mt++)
                    #pragma unroll
                    for (int nt = 0; nt < 8; nt++)
                        MMA_TF32(acc[mt][nt], ah[mt], bh[nt]);
                #pragma unroll
                for (int mt = 0; mt < 2; mt++)
                    #pragma unroll
                    for (int nt = 0; nt < 8; nt++)
                        MMA_TF32(acc[mt][nt], ah[mt], bl[nt]);
                #pragma unroll
                for (int mt = 0; mt < 2; mt++)
                    #pragma unroll
                    for (int nt = 0; nt < 8; nt++)
                        MMA_TF32(acc[mt][nt], al[mt], bh[nt]);
            }
        }

        // convert + commit next chunk to other stage
        if (c + 1 < NC) {
            float* Ah = smem + ((c + 1) & 1) * STAGE_F;
            float* Al = Ah + TILE_F;
            float* Bh = Ah + 2 * TILE_F;
            float* Bl = Ah + 3 * TILE_F;
            #pragma unroll
            for (int q = 0; q < 4; q++) {
                float4 v = ra[q];
                float hx=ftf32(v.x), hy=ftf32(v.y), hz=ftf32(v.z), hw=ftf32(v.w);
                *(float4*)(Ah + sidx[q]) = make_float4(hx, hy, hz, hw);
                *(float4*)(Al + sidx[q]) = make_float4(ftf32(v.x-hx), ftf32(v.y-hy),
                                                       ftf32(v.z-hz), ftf32(v.w-hw));
                float4 u = rb[q];
                float jx=ftf32(u.x), jy=ftf32(u.y), jz=ftf32(u.z), jw=ftf32(u.w);
                *(float4*)(Bh + sidx[q]) = make_float4(jx, jy, jz, jw);
                *(float4*)(Bl + sidx[q]) = make_float4(ftf32(u.x-jx), ftf32(u.y-jy),
                                                       ftf32(u.z-jz), ftf32(u.w-jw));
            }
        }
        __syncthreads();
    }

    // ---- epilogue: accum -> smem logits tile (aliases stage buffers) ----
    float* Ls = smem;   // [BM][LPAD] = 66048 B < 131072 B
    #pragma unroll
    for (int mt = 0; mt < 2; mt++) {
        #pragma unroll
        for (int nt = 0; nt < 8; nt++) {
            const int r_ = mrow0 + mt * 16 + g;
            const int c_ = ncol0 + nt * 8 + tg * 2;
            Ls[r_ * LPAD + c_]           = acc[mt][nt][0];
            Ls[r_ * LPAD + c_ + 1]       = acc[mt][nt][1];
            Ls[(r_ + 8) * LPAD + c_]     = acc[mt][nt][2];
            Ls[(r_ + 8) * LPAD + c_ + 1] = acc[mt][nt][3];
        }
    }
    __syncthreads();

    // per-token max & exp-sum
    if (tid < BM) {
        const float* r = Ls + tid * LPAD;
        float m = r[0];
        #pragma unroll 4
        for (int e = 1; e < E_EXP; e++) m = fmaxf(m, r[e]);
        float s = 0.0f;
        #pragma unroll 4
        for (int e = 0; e < E_EXP; e++) s += __expf(r[e] - m);
        smax[tid]  = m;
        srsum[tid] = 1.0f / s;
    }
    __syncthreads();

    // softmax probs -> smem overwrite + coalesced logits write
    for (int i = tid; i < BM * E_EXP; i += NT) {
        const int t = i >> 7;
        const int e = i & 127;
        const float p = __expf(Ls[t * LPAD + e] - smax[t]) * srsum[t];
        Ls[t * LPAD + e] = p;
        out[(size_t)(row0 + t) * E_EXP + e] = p;
    }
    __syncthreads();

    // top-8 (strict > keeps lowest index on ties) + renormalize
    if (tid < BM) {
        float* r = Ls + tid * LPAD;
        float vals[TOPK];
        int   idxs[TOPK];
        float s = 0.0f;
        #pragma unroll
        for (int k = 0; k < TOPK; k++) {
            float bv = -1.0f;
            int   bi = 0;
            for (int e = 0; e < E_EXP; e++) {
                float v = r[e];
                if (v > bv) { bv = v; bi = e; }
            }
            r[bi]   = -1.0f;
            vals[k] = bv;
            idxs[k] = bi;
            s += bv;
        }
        const float rs = 1.0f / s;
        const size_t bw = (size_t)T * E_EXP + (size_t)(row0 + tid) * TOPK;
        const size_t bx = (size_t)T * E_EXP + (size_t)T * TOPK + (size_t)(row0 + tid) * TOPK;
        #pragma unroll
        for (int k = 0; k < TOPK; k++) {
            out[bw + k] = vals[k] * rs;
            out[bx + k] = (float)idxs[k];
        }
    }
}

extern "C" void kernel_launch(void* const* d_in, const int* in_sizes, int n_in,
                              void* d_out, int out_size)
{
    const float* X = (const float*)d_in[0];   // hidden_states [T, 2048]
    const float* W = (const float*)d_in[1];   // weight        [128, 2048]
    float* out = (float*)d_out;

    const int T = in_sizes[0] / D_DIM;        // 16384
    static int configured = -1;
    if (configured < 0) {
        cudaFuncSetAttribute(router_mma,
                             cudaFuncAttributeMaxDynamicSharedMemorySize,
                             SMEM_F * (int)sizeof(float));
        configured = 1;
    }
    router_mma<<<T / BM, NT, SMEM_F * sizeof(float)>>>(X, W, out, T);
}